// round 13
// baseline (speedup 1.0000x reference)
#include <cuda_runtime.h>
#include <cstdint>

#define N_Q 16384
#define M_R 16384
#define TPB 256
#define QPT 4
#define QBLK (TPB * QPT)     // 1024 queries per CTA column
#define NQB  (N_Q / QBLK)    // 16
#define JS   18              // 16 x 18 = 288 CTAs, single wave @ occ 2
#define TJ   256             // js per smem tile (7 tiles per slice)
typedef unsigned long long u64;

__device__ u64 g_best[N_Q];              // zero-init; finisher resets via atomicExch
__device__ unsigned int g_cnt[NQB];      // zero-init; finisher resets

static __device__ __forceinline__ u64 ffma2(u64 a, u64 b, u64 c) {
    u64 d;
    asm("fma.rn.f32x2 %0, %1, %2, %3;" : "=l"(d) : "l"(a), "l"(b), "l"(c));
    return d;
}
static __device__ __forceinline__ u64 pack2(float lo, float hi) {
    u64 d;
    asm("mov.b64 %0, {%1, %2};" : "=l"(d) : "f"(lo), "f"(hi));
    return d;
}
static __device__ __forceinline__ void unpack2(u64 v, float& lo, float& hi) {
    asm("mov.b64 {%0, %1}, %2;" : "=f"(lo), "=f"(hi) : "l"(v));
}
static __device__ __forceinline__ u64 enc(float s, int j) {
    uint32_t u = __float_as_uint(s);
    uint32_t key = (u & 0x80000000u) ? ~u : (u | 0x80000000u);  // monotone f32 -> u32
    return ((u64)key << 32) | (uint32_t)(~j);                   // tie -> smaller j wins
}

__global__ void __launch_bounds__(TPB, 2) nn_kernel(const float* __restrict__ x,
                                                    const float* __restrict__ xb,
                                                    const float* __restrict__ y,
                                                    float* __restrict__ out) {
    __shared__ u64 s_w[(TJ + 1) * 8];   // 8 dim-pair packs per j + pad row
    __shared__ u64 s_c[TJ + 1];         // {c_j, 0} + pad
    __shared__ unsigned int s_fin;

    const int qb  = blockIdx.x;
    const int sl  = blockIdx.y;
    const int j0  = (sl * M_R) / JS;
    const int j1  = ((sl + 1) * M_R) / JS;
    const int tid = threadIdx.x;

    // QPT query rows, dims paired: xr[k][p] = {x[2p], x[2p+1]}
    u64 xr[QPT][8];
#pragma unroll
    for (int k = 0; k < QPT; k++) {
        const int q = qb * QBLK + k * TPB + tid;
        const float4* r = (const float4*)(x + (size_t)q * 16);
#pragma unroll
        for (int i = 0; i < 4; i++) {
            float4 v = r[i];
            xr[k][i * 2 + 0] = pack2(v.x, v.y);
            xr[k][i * 2 + 1] = pack2(v.z, v.w);
        }
    }

    float best[QPT];
    int   bidx[QPT];
#pragma unroll
    for (int k = 0; k < QPT; k++) { best[k] = -3.0e38f; bidx[k] = 0; }

    for (int jt = j0; jt < j1; jt += TJ) {
        const int cnt = min(TJ, j1 - jt);
        __syncthreads();
        // Stage w tile + fused bias computation (xb rows are L2-hot).
        {
            float4* dw = (float4*)s_w;
            const float4* srcw = ((const float4*)xb) + jt * 4;
            for (int t = tid; t < cnt * 4; t += TPB) dw[t] = srcw[t];
            for (int t = tid; t < cnt; t += TPB) {
                const float4* r = (const float4*)(xb + (size_t)(jt + t) * 16);
                float s = 0.f;
#pragma unroll
                for (int i = 0; i < 4; i++) {
                    float4 v = r[i];
                    s += v.x * v.x + v.y * v.y + v.z * v.z + v.w * v.w;
                }
                s_c[t] = pack2(-0.5f * s, 0.0f);
            }
            if (tid < 8) s_w[cnt * 8 + tid] = 0ull;   // pad row for prefetch
            if (tid == 8) s_c[cnt] = 0ull;
        }
        __syncthreads();

        u64 wpC[8], biasC;
#pragma unroll
        for (int p = 0; p < 8; p++) wpC[p] = s_w[p];
        biasC = s_c[0];

#pragma unroll 2
        for (int jj = 0; jj < cnt; jj++) {
            u64 wpN[8], biasN;
#pragma unroll
            for (int p = 0; p < 8; p++) wpN[p] = s_w[(jj + 1) * 8 + p];
            biasN = s_c[jj + 1];

            u64 acc[QPT];
#pragma unroll
            for (int k = 0; k < QPT; k++) acc[k] = biasC;
#pragma unroll
            for (int p = 0; p < 8; p++) {
#pragma unroll
                for (int k = 0; k < QPT; k++)
                    acc[k] = ffma2(xr[k][p], wpC[p], acc[k]);
            }
            const int j = jt + jj;
#pragma unroll
            for (int k = 0; k < QPT; k++) {
                float lo, hi;
                unpack2(acc[k], lo, hi);
                float s = lo + hi;
                if (s > best[k]) { best[k] = s; bidx[k] = j; }   // strict > == first index
            }
#pragma unroll
            for (int p = 0; p < 8; p++) wpC[p] = wpN[p];
            biasC = biasN;
        }
    }

    // Publish partials.
#pragma unroll
    for (int k = 0; k < QPT; k++) {
        const int q = qb * QBLK + k * TPB + tid;
        atomicMax(&g_best[q], enc(best[k], bidx[k]));
    }
    __threadfence();

    // Last CTA of this query column finishes: gather + reset for next replay.
    if (tid == 0) s_fin = (atomicAdd(&g_cnt[qb], 1u) == JS - 1) ? 1u : 0u;
    __syncthreads();
    if (s_fin) {
        __threadfence();   // order counter-acquire before reading partials
#pragma unroll
        for (int k = 0; k < QPT; k++) {
            const int q = qb * QBLK + k * TPB + tid;
            u64 v = atomicExch(&g_best[q], 0ull);   // read winner + reset in one op
            out[q] = y[(int)(~(uint32_t)v)];
        }
        if (tid == 0) g_cnt[qb] = 0u;               // reset counter for next replay
    }
}

extern "C" void kernel_launch(void* const* d_in, const int* in_sizes, int n_in,
                              void* d_out, int out_size) {
    const float* x  = (const float*)d_in[0];
    const float* xb = (const float*)d_in[1];
    const float* y  = (const float*)d_in[2];
    float* out = (float*)d_out;

    dim3 grid(NQB, JS);          // 16 x 18 = 288 CTAs
    nn_kernel<<<grid, TPB>>>(x, xb, y, out);
}

// round 14
// speedup vs baseline: 1.4729x; 1.4729x over previous
#include <cuda_runtime.h>
#include <cstdint>

#define N_Q 16384
#define M_R 16384
#define TPB 256
#define QPT 4
#define JS  18          // 16 x 18 = 288 CTAs, single wave @ occ 2
#define TJ  128         // js per smem tile
typedef unsigned long long u64;

__device__ u64 g_best[N_Q];    // zero-init at load; gather self-resets each replay

static __device__ __forceinline__ u64 ffma2(u64 a, u64 b, u64 c) {
    u64 d;
    asm("fma.rn.f32x2 %0, %1, %2, %3;" : "=l"(d) : "l"(a), "l"(b), "l"(c));
    return d;
}
static __device__ __forceinline__ u64 pack2(float lo, float hi) {
    u64 d;
    asm("mov.b64 %0, {%1, %2};" : "=l"(d) : "f"(lo), "f"(hi));
    return d;
}
static __device__ __forceinline__ void unpack2(u64 v, float& lo, float& hi) {
    asm("mov.b64 {%0, %1}, %2;" : "=f"(lo), "=f"(hi) : "l"(v));
}
static __device__ __forceinline__ u64 enc(float s, int j) {
    uint32_t u = __float_as_uint(s);
    uint32_t key = (u & 0x80000000u) ? ~u : (u | 0x80000000u);  // monotone f32 -> u32
    return ((u64)key << 32) | (uint32_t)(~j);                   // tie -> smaller j wins
}

// ---- main scan: tiled, software-pipelined, prep fused into staging ----
__global__ void __launch_bounds__(TPB, 2) nn_kernel(const float* __restrict__ x,
                                                    const float* __restrict__ xb) {
    __shared__ u64 s_w[(TJ + 1) * 8];   // 8 dim-pair packs per j + 1 pad row
    __shared__ u64 s_c[TJ + 1];         // {c_j, 0} + pad

    const int qb  = blockIdx.x;
    const int sl  = blockIdx.y;
    const int j0  = (sl * M_R) / JS;
    const int j1  = ((sl + 1) * M_R) / JS;
    const int tid = threadIdx.x;

    // QPT query rows, dims paired: xr[k][p] = {x[2p], x[2p+1]}
    u64 xr[QPT][8];
#pragma unroll
    for (int k = 0; k < QPT; k++) {
        const int q = qb * (TPB * QPT) + k * TPB + tid;
        const float4* r = (const float4*)(x + (size_t)q * 16);
#pragma unroll
        for (int i = 0; i < 4; i++) {
            float4 v = r[i];
            xr[k][i * 2 + 0] = pack2(v.x, v.y);
            xr[k][i * 2 + 1] = pack2(v.z, v.w);
        }
    }

    float best[QPT];
    int   bidx[QPT];
#pragma unroll
    for (int k = 0; k < QPT; k++) { best[k] = -3.0e38f; bidx[k] = 0; }

    for (int jt = j0; jt < j1; jt += TJ) {
        const int cnt = min(TJ, j1 - jt);
        __syncthreads();
        // Stage w tile (coalesced float4) + compute bias c_j from gmem (L2-hot rows).
        {
            float4* dw = (float4*)s_w;
            const float4* srcw = ((const float4*)xb) + jt * 4;
            for (int t = tid; t < cnt * 4; t += TPB) dw[t] = srcw[t];
            if (tid < cnt) {
                const float4* r = (const float4*)(xb + (size_t)(jt + tid) * 16);
                float s = 0.f;
#pragma unroll
                for (int i = 0; i < 4; i++) {
                    float4 v = r[i];
                    s += v.x * v.x + v.y * v.y + v.z * v.z + v.w * v.w;
                }
                s_c[tid] = pack2(-0.5f * s, 0.0f);
            }
            if (tid >= cnt && tid < cnt + 8) s_w[cnt * 8 + (tid - cnt)] = 0ull;
            if (tid == TPB - 1) s_c[cnt] = 0ull;   // pad bias for prefetch
        }
        __syncthreads();

        // Pipeline prologue: row 0.
        u64 wpC[8], biasC;
#pragma unroll
        for (int p = 0; p < 8; p++) wpC[p] = s_w[p];
        biasC = s_c[0];

#pragma unroll 2
        for (int jj = 0; jj < cnt; jj++) {
            // Prefetch row jj+1: LDS latency overlaps the FFMA2 block below.
            u64 wpN[8], biasN;
#pragma unroll
            for (int p = 0; p < 8; p++) wpN[p] = s_w[(jj + 1) * 8 + p];
            biasN = s_c[jj + 1];

            u64 acc[QPT];
#pragma unroll
            for (int k = 0; k < QPT; k++) acc[k] = biasC;
#pragma unroll
            for (int p = 0; p < 8; p++) {
#pragma unroll
                for (int k = 0; k < QPT; k++)
                    acc[k] = ffma2(xr[k][p], wpC[p], acc[k]);
            }
            const int j = jt + jj;
#pragma unroll
            for (int k = 0; k < QPT; k++) {
                float lo, hi;
                unpack2(acc[k], lo, hi);
                float s = lo + hi;
                bool gt = s > best[k];               // FSETP: feeds only the index SEL
                bidx[k] = gt ? j : bidx[k];          // off the loop-carry
                best[k] = fmaxf(best[k], s);         // FMNMX: short (8-cyc) carry
            }
#pragma unroll
            for (int p = 0; p < 8; p++) wpC[p] = wpN[p];
            biasC = biasN;
        }
    }

#pragma unroll
    for (int k = 0; k < QPT; k++) {
        const int q = qb * (TPB * QPT) + k * TPB + tid;
        atomicMax(&g_best[q], enc(best[k], bidx[k]));
    }
}

// ---- gather + self-reset (next replay starts from zeroed accumulators) ----
__global__ void gather_kernel(const float* __restrict__ y, float* __restrict__ out) {
    int q = blockIdx.x * blockDim.x + threadIdx.x;
    if (q >= N_Q) return;
    u64 v = g_best[q];
    int j = (int)(~(uint32_t)v);
    out[q] = y[j];
    g_best[q] = 0ull;
}

extern "C" void kernel_launch(void* const* d_in, const int* in_sizes, int n_in,
                              void* d_out, int out_size) {
    const float* x  = (const float*)d_in[0];
    const float* xb = (const float*)d_in[1];
    const float* y  = (const float*)d_in[2];
    float* out = (float*)d_out;

    dim3 grid(N_Q / (TPB * QPT), JS);          // 16 x 18 = 288 CTAs
    nn_kernel<<<grid, TPB>>>(x, xb);
    gather_kernel<<<N_Q / 256, 256>>>(y, out);
}